// round 14
// baseline (speedup 1.0000x reference)
#include <cuda_runtime.h>

#define NBLOCKS 1184     // 148 SMs x 8 resident blocks -> exactly ONE wave @ 32 regs
#define NTHREADS 256

// Scratch via __device__ globals (no allocs allowed).
__device__ float        g_partial[NBLOCKS];
__device__ unsigned int g_count;   // zero-init at load; reset by last block each run

// 128-bit non-coherent load with a 256B L2 prefetch hint: encourages full
// 256B DRAM bursts on this purely-streaming access pattern.
__device__ __forceinline__ float4 ldg128_l2_256(const float4* p) {
    float4 v;
    asm("ld.global.nc.L2::256B.v4.f32 {%0,%1,%2,%3}, [%4];"
        : "=f"(v.x), "=f"(v.y), "=f"(v.z), "=f"(v.w)
        : "l"(p));
    return v;
}

// 16 lanes cooperate on one row of D=64 floats (1 float4 per lane per tensor).
// 2-row unroll with grid-strided pairing (r, r+ngroups) — measured-best
// inter-warp address interleave across 13 tested variants. Labels loaded as
// broadcast in flight with the float4s so lane 0 has no dependent load after
// the shuffle reduction.
__global__ void __launch_bounds__(NTHREADS, 8)
speaker_loss_kernel(const int* __restrict__ s,
                    const float* __restrict__ vs,
                    const int* __restrict__ other_s,
                    const float* __restrict__ other_vs,
                    float* __restrict__ out, int B) {
    const int tid     = blockIdx.x * blockDim.x + threadIdx.x;
    const int group   = tid >> 4;
    const int lane16  = tid & 15;
    const int ngroups = (gridDim.x * blockDim.x) >> 4;
    const unsigned hmask = 0xFFFFu << (threadIdx.x & 16);

    float acc = 0.0f;

    int r = group;
    const int step2 = ngroups * 2;

    for (; r + ngroups < B; r += step2) {
        const int r0 = r, r1 = r + ngroups;

        const float4 x0 = ldg128_l2_256(reinterpret_cast<const float4*>(vs + (size_t)r0 * 64) + lane16);
        const float4 x1 = ldg128_l2_256(reinterpret_cast<const float4*>(vs + (size_t)r1 * 64) + lane16);
        const float4 y0 = ldg128_l2_256(reinterpret_cast<const float4*>(other_vs + (size_t)r0 * 64) + lane16);
        const float4 y1 = ldg128_l2_256(reinterpret_cast<const float4*>(other_vs + (size_t)r1 * 64) + lane16);

        // Broadcast label loads (same address across the group): in flight with
        // the vector loads, consumed only after the shuffle reduction.
        const int sa0 = __ldg(&s[r0]),       sa1 = __ldg(&s[r1]);
        const int sb0 = __ldg(&other_s[r0]), sb1 = __ldg(&other_s[r1]);

        float d0x = x0.x - y0.x, d0y = x0.y - y0.y, d0z = x0.z - y0.z, d0w = x0.w - y0.w;
        float d1x = x1.x - y1.x, d1y = x1.y - y1.y, d1z = x1.z - y1.z, d1w = x1.w - y1.w;

        float p0 = d0x * d0x + d0y * d0y + d0z * d0z + d0w * d0w;
        float p1 = d1x * d1x + d1y * d1y + d1z * d1z + d1w * d1w;

        #pragma unroll
        for (int off = 8; off > 0; off >>= 1) {
            p0 += __shfl_xor_sync(hmask, p0, off);
            p1 += __shfl_xor_sync(hmask, p1, off);
        }

        if (lane16 == 0) {
            const float v0 = (sa0 != sb0) ? fmaxf(1.0f - p0, 0.0f) : p0;
            const float v1 = (sa1 != sb1) ? fmaxf(1.0f - p1, 0.0f) : p1;
            acc += v0 + v1;
        }
    }

    // Tail (<=1 row per group).
    for (; r < B; r += ngroups) {
        const float4 x = __ldg(reinterpret_cast<const float4*>(vs + (size_t)r * 64) + lane16);
        const float4 y = __ldg(reinterpret_cast<const float4*>(other_vs + (size_t)r * 64) + lane16);
        const int sa = __ldg(&s[r]), sb = __ldg(&other_s[r]);
        float dx = x.x - y.x, dy = x.y - y.y, dz = x.z - y.z, dw = x.w - y.w;
        float p = dx * dx + dy * dy + dz * dz + dw * dw;
        #pragma unroll
        for (int off = 8; off > 0; off >>= 1)
            p += __shfl_xor_sync(hmask, p, off);
        if (lane16 == 0) {
            if (sa != sb) p = fmaxf(1.0f - p, 0.0f);
            acc += p;
        }
    }

    // ---- Block reduction ----
    #pragma unroll
    for (int off = 16; off > 0; off >>= 1)
        acc += __shfl_xor_sync(0xFFFFFFFFu, acc, off);

    __shared__ float warpsum[NTHREADS / 32];
    __shared__ bool  is_last;
    const int wid = threadIdx.x >> 5;
    const int lid = threadIdx.x & 31;
    if (lid == 0) warpsum[wid] = acc;
    __syncthreads();

    if (threadIdx.x == 0) {
        float bsum = 0.0f;
        #pragma unroll
        for (int i = 0; i < NTHREADS / 32; i++) bsum += warpsum[i];
        g_partial[blockIdx.x] = bsum;
        __threadfence();
        unsigned int prev = atomicAdd(&g_count, 1u);
        is_last = (prev == gridDim.x - 1);
    }
    __syncthreads();

    // ---- Last block finalizes: reduce partials, write out, reset counter ----
    if (is_last) {
        double v = 0.0;
        for (int i = threadIdx.x; i < (int)gridDim.x; i += blockDim.x)
            v += (double)g_partial[i];
        #pragma unroll
        for (int off = 16; off > 0; off >>= 1) {
            double o = __longlong_as_double(
                __shfl_xor_sync(0xFFFFFFFFu, __double_as_longlong(v), off));
            v += o;
        }
        __shared__ double wsum2[NTHREADS / 32];
        if (lid == 0) wsum2[wid] = v;
        __syncthreads();
        if (threadIdx.x == 0) {
            double t = 0.0;
            #pragma unroll
            for (int i = 0; i < NTHREADS / 32; i++) t += wsum2[i];
            out[0] = (float)(t / (double)B);
            g_count = 0;   // reset for next graph replay
        }
    }
}

extern "C" void kernel_launch(void* const* d_in, const int* in_sizes, int n_in,
                              void* d_out, int out_size) {
    const int*   s        = (const int*)d_in[0];
    const float* vs       = (const float*)d_in[1];
    const int*   other_s  = (const int*)d_in[2];
    const float* other_vs = (const float*)d_in[3];
    float*       out      = (float*)d_out;

    const int B = in_sizes[0];

    speaker_loss_kernel<<<NBLOCKS, NTHREADS>>>(s, vs, other_s, other_vs, out, B);
}

// round 16
// speedup vs baseline: 1.0282x; 1.0282x over previous
#include <cuda_runtime.h>

#define NBLOCKS 888      // 148 SMs x 6 resident -> single co-resident wave @ ~40 regs
#define NTHREADS 256

// Scratch via __device__ globals (no allocs allowed).
__device__ float        g_partial[NBLOCKS];
__device__ unsigned int g_count;   // zero-init at load; reset by last block each run

// Blackwell 256-bit streaming load with evict-first L2 policy (only legal on
// .v8.b32 width): zero-reuse stream -> lines marked dead-on-arrival in L2,
// plus 256B prefetch hint for full DRAM bursts.
__device__ __forceinline__ void ldg256_stream(const float* __restrict__ p, float r[8]) {
    asm("ld.global.nc.L2::evict_first.L2::256B.v8.f32 {%0,%1,%2,%3,%4,%5,%6,%7}, [%8];"
        : "=f"(r[0]), "=f"(r[1]), "=f"(r[2]), "=f"(r[3]),
          "=f"(r[4]), "=f"(r[5]), "=f"(r[6]), "=f"(r[7])
        : "l"(p));
}

// 8 lanes cooperate on one row of D=64 floats (8 floats = 32B per lane per tensor).
__global__ void __launch_bounds__(NTHREADS, 6)
speaker_loss_kernel(const int* __restrict__ s,
                    const float* __restrict__ vs,
                    const int* __restrict__ other_s,
                    const float* __restrict__ other_vs,
                    float* __restrict__ out, int B) {
    const int tid     = blockIdx.x * blockDim.x + threadIdx.x;
    const int group   = tid >> 3;            // 8-lane group id
    const int lane8   = tid & 7;
    const int ngroups = (gridDim.x * blockDim.x) >> 3;
    // Mask covering only this 8-lane octet (safe under trip-count divergence).
    const unsigned omask = 0xFFu << (threadIdx.x & 24);

    float acc = 0.0f;

    for (int r = group; r < B; r += ngroups) {
        const float* px = vs       + (size_t)r * 64 + lane8 * 8;
        const float* py = other_vs + (size_t)r * 64 + lane8 * 8;
        float x[8], y[8];
        ldg256_stream(px, x);
        ldg256_stream(py, y);

        // Broadcast label loads, in flight with the vector loads.
        const int sa = __ldg(&s[r]);
        const int sb = __ldg(&other_s[r]);

        float p = 0.0f;
        #pragma unroll
        for (int i = 0; i < 8; i++) {
            float d = x[i] - y[i];
            p += d * d;
        }

        // Reduce over the 8 lanes of this octet.
        #pragma unroll
        for (int off = 4; off > 0; off >>= 1)
            p += __shfl_xor_sync(omask, p, off);

        if (lane8 == 0) {
            if (sa != sb)
                p = fmaxf(1.0f - p, 0.0f);   // L = 1.0 hinge
            acc += p;
        }
    }

    // ---- Block reduction ----
    #pragma unroll
    for (int off = 16; off > 0; off >>= 1)
        acc += __shfl_xor_sync(0xFFFFFFFFu, acc, off);

    __shared__ float warpsum[NTHREADS / 32];
    __shared__ bool  is_last;
    const int wid = threadIdx.x >> 5;
    const int lid = threadIdx.x & 31;
    if (lid == 0) warpsum[wid] = acc;
    __syncthreads();

    if (threadIdx.x == 0) {
        float bsum = 0.0f;
        #pragma unroll
        for (int i = 0; i < NTHREADS / 32; i++) bsum += warpsum[i];
        g_partial[blockIdx.x] = bsum;
        __threadfence();
        unsigned int prev = atomicAdd(&g_count, 1u);
        is_last = (prev == gridDim.x - 1);
    }
    __syncthreads();

    // ---- Last block finalizes: reduce partials, write out, reset counter ----
    if (is_last) {
        double v = 0.0;
        for (int i = threadIdx.x; i < (int)gridDim.x; i += blockDim.x)
            v += (double)g_partial[i];
        #pragma unroll
        for (int off = 16; off > 0; off >>= 1) {
            double o = __longlong_as_double(
                __shfl_xor_sync(0xFFFFFFFFu, __double_as_longlong(v), off));
            v += o;
        }
        __shared__ double wsum2[NTHREADS / 32];
        if (lid == 0) wsum2[wid] = v;
        __syncthreads();
        if (threadIdx.x == 0) {
            double t = 0.0;
            #pragma unroll
            for (int i = 0; i < NTHREADS / 32; i++) t += wsum2[i];
            out[0] = (float)(t / (double)B);
            g_count = 0;   // reset for next graph replay
        }
    }
}

extern "C" void kernel_launch(void* const* d_in, const int* in_sizes, int n_in,
                              void* d_out, int out_size) {
    const int*   s        = (const int*)d_in[0];
    const float* vs       = (const float*)d_in[1];
    const int*   other_s  = (const int*)d_in[2];
    const float* other_vs = (const float*)d_in[3];
    float*       out      = (float*)d_out;

    const int B = in_sizes[0];

    speaker_loss_kernel<<<NBLOCKS, NTHREADS>>>(s, vs, other_s, other_vs, out, B);
}